// round 8
// baseline (speedup 1.0000x reference)
#include <cuda_runtime.h>
#include <cuda_bf16.h>
#include <stdint.h>

#define D_MODEL 4096
#define RANK    32
#define TOKT    128          // tokens per CTA tile
#define COLT    128          // columns per CTA tile
#define THREADS 256
#define SA      80           // bytes per sA row: 32 bf16 + 8 pad
#define SB      80           // bytes per sB row: 32 bf16 + 8 pad
#define SL      264          // bytes per sLora row: 128 bf16 + 8 pad

#define OFF_IDS  16
#define OFF_A    1024                    // A-tile: 128*80 = 10240 (overlaid by sLora later)
#define OFF_LORA 1024                    // sLora: 128*264 = 33792 -> ends 34816
#define OFF_B    34816                   // B-tile: 128*80 = 10240
#define SM_TOTAL (OFF_B + COLT * SB)     // 45056 < 48KB static limit

__device__ __forceinline__ unsigned h2u(__nv_bfloat162 h) {
    return *reinterpret_cast<unsigned*>(&h);
}
__device__ __forceinline__ __nv_bfloat162 u2h(unsigned u) {
    return *reinterpret_cast<__nv_bfloat162*>(&u);
}

// HMMA bf16: D(16x8,f32) += A(16x16) * B(16x8)  — sm_80+, legal on compute_103
__device__ __forceinline__ void mma16816(float& d0, float& d1, float& d2, float& d3,
                                         unsigned a0, unsigned a1, unsigned a2, unsigned a3,
                                         unsigned b0, unsigned b1) {
    asm volatile("mma.sync.aligned.m16n8k16.row.col.f32.bf16.bf16.f32 "
                 "{%0,%1,%2,%3}, {%4,%5,%6,%7}, {%8,%9}, {%0,%1,%2,%3};"
                 : "+f"(d0), "+f"(d1), "+f"(d2), "+f"(d3)
                 : "r"(a0), "r"(a1), "r"(a2), "r"(a3), "r"(b0), "r"(b1));
}

__global__ void __launch_bounds__(THREADS)
emb_lora_mma(const int* __restrict__ ids, const int* __restrict__ wq,
             const float* __restrict__ wscale, const float* __restrict__ A,
             const float* __restrict__ Bm, float* __restrict__ out, int ntok)
{
    __shared__ __align__(16) unsigned char sm[SM_TOTAL];

    const int tid  = threadIdx.x;
    const int wid  = tid >> 5;
    const int lane = tid & 31;
    const int g    = lane >> 2;       // mma groupID (0..7)
    const int tig  = lane & 3;        // thread-in-group
    const int t0   = blockIdx.y * TOKT;
    const int col0 = blockIdx.x * COLT;
    int* sIds = (int*)(sm + OFF_IDS);

    // ids cache
    if (tid < TOKT) {
        int t = t0 + tid;
        sIds[tid] = (t < ntok) ? __ldg(ids + t) : 0;
    }

    // dtype probe: widened base table float32 vs int32 (uniform across threads)
    int isf = 0;
    #pragma unroll
    for (int i = 0; i < 16; ++i) {
        unsigned u = __ldg((const unsigned*)wq + i);
        if (u == 0u) continue;
        unsigned e = (u >> 23) & 0xFFu;
        isf = (e != 0u && e != 0xFFu);
        break;
    }
    __syncthreads();

    // ---- build bf16 A-tile [tok][k], SCALING=0.5 folded (exact pow2) ----
    #pragma unroll
    for (int i = 0; i < 8; ++i) {
        int p  = tid + i * THREADS;          // 0..2047
        int tl = p >> 4, kp = p & 15;        // token, k-pair
        int id = sIds[tl];
        float2 v = *reinterpret_cast<const float2*>(A + (size_t)id * RANK + 2 * kp);
        *reinterpret_cast<unsigned*>(sm + OFF_A + tl * SA + kp * 4) =
            h2u(__floats2bfloat162_rn(v.x * 0.5f, v.y * 0.5f));
    }
    // ---- build bf16 B-tile [n][k] (transpose of Bm[k][n]) ----
    #pragma unroll
    for (int i = 0; i < 8; ++i) {
        int p  = tid + i * THREADS;
        int n  = p & 127, kp = p >> 7;       // n fastest -> coalesced global reads
        const float* bp = Bm + (size_t)(2 * kp) * D_MODEL + col0 + n;
        *reinterpret_cast<unsigned*>(sm + OFF_B + n * SB + kp * 4) =
            h2u(__floats2bfloat162_rn(__ldg(bp), __ldg(bp + D_MODEL)));
    }
    __syncthreads();

    // ---- A fragments for this warp's 16 token rows -> registers ----
    const int tb = wid * 16;
    const unsigned char* ar = sm + OFF_A + (tb + g) * SA + tig * 4;
    const unsigned a0l = *(const unsigned*)(ar);
    const unsigned a1l = *(const unsigned*)(ar + 8 * SA);
    const unsigned a2l = *(const unsigned*)(ar + 16);
    const unsigned a3l = *(const unsigned*)(ar + 8 * SA + 16);
    const unsigned a0h = *(const unsigned*)(ar + 32);
    const unsigned a1h = *(const unsigned*)(ar + 8 * SA + 32);
    const unsigned a2h = *(const unsigned*)(ar + 48);
    const unsigned a3h = *(const unsigned*)(ar + 8 * SA + 48);
    __syncthreads();   // everyone's frags loaded before sLora overwrites A region

    // ---- compute 16 n-blocks (all 128 cols), store lora (bf16) to sLora ----
    #pragma unroll
    for (int nb = 0; nb < 16; ++nb) {
        const unsigned char* bb = sm + OFF_B + (nb * 8 + g) * SB + tig * 4;
        unsigned b0l = *(const unsigned*)(bb);
        unsigned b1l = *(const unsigned*)(bb + 16);
        unsigned b0h = *(const unsigned*)(bb + 32);
        unsigned b1h = *(const unsigned*)(bb + 48);
        float d0 = 0.f, d1 = 0.f, d2 = 0.f, d3 = 0.f;
        mma16816(d0, d1, d2, d3, a0l, a1l, a2l, a3l, b0l, b1l);
        mma16816(d0, d1, d2, d3, a0h, a1h, a2h, a3h, b0h, b1h);
        int colp = nb * 8 + 2 * tig;   // col (0..127)
        *reinterpret_cast<unsigned*>(sm + OFF_LORA + (tb + g) * SL + colp * 2) =
            h2u(__floats2bfloat162_rn(d0, d1));
        *reinterpret_cast<unsigned*>(sm + OFF_LORA + (tb + g + 8) * SL + colp * 2) =
            h2u(__floats2bfloat162_rn(d2, d3));
    }
    __syncthreads();

    const float scale = __ldg(wscale);

    // ---- fused epilogue: 512B/row gathers, MLP=4 batching, float4 stores ----
    #pragma unroll
    for (int jj = 0; jj < 16; jj += 4) {
        int4 q[4];
        unsigned lv0[4], lv1[4];
        #pragma unroll
        for (int u = 0; u < 4; ++u) {
            int tl = tb + jj + u;
            int id = sIds[tl];
            q[u] = __ldg(reinterpret_cast<const int4*>(
                       wq + (size_t)id * D_MODEL + col0) + lane);
            const unsigned* lp = reinterpret_cast<const unsigned*>(
                sm + OFF_LORA + tl * SL + lane * 8);
            lv0[u] = lp[0]; lv1[u] = lp[1];
        }
        #pragma unroll
        for (int u = 0; u < 4; ++u) {
            int t = t0 + tb + jj + u;
            if (t < ntok) {
                __nv_bfloat162 l0 = u2h(lv0[u]), l1 = u2h(lv1[u]);
                float bx = isf ? __int_as_float(q[u].x) : (float)q[u].x;
                float by = isf ? __int_as_float(q[u].y) : (float)q[u].y;
                float bz = isf ? __int_as_float(q[u].z) : (float)q[u].z;
                float bw = isf ? __int_as_float(q[u].w) : (float)q[u].w;
                float4 o;
                o.x = fmaf(bx, scale, __bfloat162float(l0.x));
                o.y = fmaf(by, scale, __bfloat162float(l0.y));
                o.z = fmaf(bz, scale, __bfloat162float(l1.x));
                o.w = fmaf(bw, scale, __bfloat162float(l1.y));
                *reinterpret_cast<float4*>(
                    out + (size_t)t * D_MODEL + col0 + lane * 4) = o;
            }
        }
    }
}

extern "C" void kernel_launch(void* const* d_in, const int* in_sizes, int n_in,
                              void* d_out, int out_size) {
    // Bind inputs by UNIQUE element counts (robust to metadata ordering).
    const int*   ids    = nullptr;
    const int*   wq     = nullptr;
    const float* wscale = nullptr;
    const float* A      = nullptr;
    const float* Bm     = nullptr;

    long long ntok_ll = (long long)out_size / D_MODEL;
    long long wq_sz = 0;
    int wq_idx = -1;
    for (int i = 0; i < n_in; ++i)
        if ((long long)in_sizes[i] > wq_sz) { wq_sz = in_sizes[i]; wq_idx = i; }
    wq = (const int*)d_in[wq_idx];

    for (int i = 0; i < n_in; ++i) {
        if (i == wq_idx) continue;
        long long s = in_sizes[i];
        if (s == 1)                              wscale = (const float*)d_in[i];
        else if (s == ntok_ll)                   ids    = (const int*)d_in[i];
        else if (s == (long long)RANK * D_MODEL) Bm     = (const float*)d_in[i];
        else                                     A      = (const float*)d_in[i];
    }

    const int ntok = (int)ntok_ll;                        // 16384
    dim3 grid(D_MODEL / COLT, (ntok + TOKT - 1) / TOKT);  // (32, 128)
    emb_lora_mma<<<grid, THREADS>>>(ids, wq, wscale, A, Bm, (float*)d_out, ntok);
}

// round 9
// speedup vs baseline: 1.1234x; 1.1234x over previous
#include <cuda_runtime.h>
#include <cuda_bf16.h>
#include <stdint.h>

#define D_MODEL 4096
#define RANK    32
#define TOKT    128          // tokens per CTA tile
#define COLT    128          // columns per CTA tile
#define THREADS 256
#define SA      80           // bytes per sA row: 32 bf16 + 8 pad
#define SB      80           // bytes per sB row: 32 bf16 + 8 pad
#define SL      136          // bytes per sLora row: 64 bf16 + 8 pad

// Layout (28KB total -> 8 CTAs/SM):
//   [16..528)      sIds
//   [1024..11264)  B-tile   (pass0 reads rows 0..63 -> bytes <6144;
//                            pass1 reads rows 64..127 -> bytes <11264)
//   [11264..21504) A-tile   (only until fragments are in registers)
//   [11264..28672) sLora    (overlays A + tail; written after frag loads)
#define OFF_IDS  16
#define OFF_B    1024
#define OFF_A    11264
#define OFF_LORA 11264
#define SM_TOTAL 28672

__device__ __forceinline__ unsigned h2u(__nv_bfloat162 h) {
    return *reinterpret_cast<unsigned*>(&h);
}

// HMMA bf16: D(16x8,f32) += A(16x16) * B(16x8)  — sm_80+, legal on compute_103
__device__ __forceinline__ void mma16816(float& d0, float& d1, float& d2, float& d3,
                                         unsigned a0, unsigned a1, unsigned a2, unsigned a3,
                                         unsigned b0, unsigned b1) {
    asm volatile("mma.sync.aligned.m16n8k16.row.col.f32.bf16.bf16.f32 "
                 "{%0,%1,%2,%3}, {%4,%5,%6,%7}, {%8,%9}, {%0,%1,%2,%3};"
                 : "+f"(d0), "+f"(d1), "+f"(d2), "+f"(d3)
                 : "r"(a0), "r"(a1), "r"(a2), "r"(a3), "r"(b0), "r"(b1));
}

__global__ void __launch_bounds__(THREADS)
emb_lora_mma(const int* __restrict__ ids, const int* __restrict__ wq,
             const float* __restrict__ wscale, const float* __restrict__ A,
             const float* __restrict__ Bm, float* __restrict__ out, int ntok)
{
    __shared__ __align__(16) unsigned char sm[SM_TOTAL];

    const int tid  = threadIdx.x;
    const int wid  = tid >> 5;
    const int lane = tid & 31;
    const int g    = lane >> 2;       // mma groupID (0..7)
    const int tig  = lane & 3;        // thread-in-group
    const int t0   = blockIdx.y * TOKT;
    const int col0 = blockIdx.x * COLT;
    int* sIds = (int*)(sm + OFF_IDS);

    // ids cache
    if (tid < TOKT) {
        int t = t0 + tid;
        sIds[tid] = (t < ntok) ? __ldg(ids + t) : 0;
    }

    // dtype probe: widened base table float32 vs int32 (uniform across threads)
    int isf = 0;
    #pragma unroll
    for (int i = 0; i < 16; ++i) {
        unsigned u = __ldg((const unsigned*)wq + i);
        if (u == 0u) continue;
        unsigned e = (u >> 23) & 0xFFu;
        isf = (e != 0u && e != 0xFFu);
        break;
    }
    __syncthreads();

    // ---- build bf16 A-tile [tok][k], SCALING=0.5 folded (exact pow2) ----
    #pragma unroll
    for (int i = 0; i < 8; ++i) {
        int p  = tid + i * THREADS;          // 0..2047
        int tl = p >> 4, kp = p & 15;        // token, k-pair
        int id = sIds[tl];
        float2 v = *reinterpret_cast<const float2*>(A + (size_t)id * RANK + 2 * kp);
        *reinterpret_cast<unsigned*>(sm + OFF_A + tl * SA + kp * 4) =
            h2u(__floats2bfloat162_rn(v.x * 0.5f, v.y * 0.5f));
    }
    // ---- build bf16 B-tile [n][k] (transpose of Bm[k][n]) ----
    #pragma unroll
    for (int i = 0; i < 8; ++i) {
        int p  = tid + i * THREADS;
        int n  = p & 127, kp = p >> 7;       // n fastest -> coalesced global reads
        const float* bp = Bm + (size_t)(2 * kp) * D_MODEL + col0 + n;
        *reinterpret_cast<unsigned*>(sm + OFF_B + n * SB + kp * 4) =
            h2u(__floats2bfloat162_rn(__ldg(bp), __ldg(bp + D_MODEL)));
    }
    __syncthreads();

    // ---- A fragments for this warp's 16 token rows -> registers ----
    const int tb = wid * 16;
    const unsigned char* ar = sm + OFF_A + (tb + g) * SA + tig * 4;
    const unsigned a0l = *(const unsigned*)(ar);
    const unsigned a1l = *(const unsigned*)(ar + 8 * SA);
    const unsigned a2l = *(const unsigned*)(ar + 16);
    const unsigned a3l = *(const unsigned*)(ar + 8 * SA + 16);
    const unsigned a0h = *(const unsigned*)(ar + 32);
    const unsigned a1h = *(const unsigned*)(ar + 8 * SA + 32);
    const unsigned a2h = *(const unsigned*)(ar + 48);
    const unsigned a3h = *(const unsigned*)(ar + 8 * SA + 48);
    __syncthreads();   // all frags in registers before sLora overlays A

    const float scale = __ldg(wscale);

    #pragma unroll
    for (int c = 0; c < 2; ++c) {      // two 64-col passes
        // ---- compute 8 n-blocks, store lora (bf16) to sLora ----
        #pragma unroll
        for (int nb = 0; nb < 8; ++nb) {
            const unsigned char* bb = sm + OFF_B + (c * 64 + nb * 8 + g) * SB + tig * 4;
            unsigned b0l = *(const unsigned*)(bb);
            unsigned b1l = *(const unsigned*)(bb + 16);
            unsigned b0h = *(const unsigned*)(bb + 32);
            unsigned b1h = *(const unsigned*)(bb + 48);
            float d0 = 0.f, d1 = 0.f, d2 = 0.f, d3 = 0.f;
            mma16816(d0, d1, d2, d3, a0l, a1l, a2l, a3l, b0l, b1l);
            mma16816(d0, d1, d2, d3, a0h, a1h, a2h, a3h, b0h, b1h);
            int colp = nb * 8 + 2 * tig;   // col within pass (0..63)
            *reinterpret_cast<unsigned*>(sm + OFF_LORA + (tb + g) * SL + colp * 2) =
                h2u(__floats2bfloat162_rn(d0, d1));
            *reinterpret_cast<unsigned*>(sm + OFF_LORA + (tb + g + 8) * SL + colp * 2) =
                h2u(__floats2bfloat162_rn(d2, d3));
        }
        __syncthreads();

        // ---- fused epilogue: coalesced gather + add + store, 64 cols ----
        const int colb = col0 + 64 * c;
        #pragma unroll 4
        for (int j = 0; j < 16; ++j) {
            int tl = tb + j;
            int t  = t0 + tl;
            if (t < ntok) {
                int id = sIds[tl];
                int2 q = __ldg(reinterpret_cast<const int2*>(
                             wq + (size_t)id * D_MODEL + colb) + lane);
                unsigned lvu = *reinterpret_cast<const unsigned*>(
                    sm + OFF_LORA + tl * SL + lane * 4);
                __nv_bfloat162 lv = *reinterpret_cast<__nv_bfloat162*>(&lvu);
                float bx = isf ? __int_as_float(q.x) : (float)q.x;
                float by = isf ? __int_as_float(q.y) : (float)q.y;
                float2 o = make_float2(fmaf(bx, scale, __bfloat162float(lv.x)),
                                       fmaf(by, scale, __bfloat162float(lv.y)));
                *reinterpret_cast<float2*>(
                    out + (size_t)t * D_MODEL + colb + lane * 2) = o;
            }
        }
        __syncthreads();   // protect sLora before next pass overwrites
    }
}

extern "C" void kernel_launch(void* const* d_in, const int* in_sizes, int n_in,
                              void* d_out, int out_size) {
    // Bind inputs by UNIQUE element counts (robust to metadata ordering).
    const int*   ids    = nullptr;
    const int*   wq     = nullptr;
    const float* wscale = nullptr;
    const float* A      = nullptr;
    const float* Bm     = nullptr;

    long long ntok_ll = (long long)out_size / D_MODEL;
    long long wq_sz = 0;
    int wq_idx = -1;
    for (int i = 0; i < n_in; ++i)
        if ((long long)in_sizes[i] > wq_sz) { wq_sz = in_sizes[i]; wq_idx = i; }
    wq = (const int*)d_in[wq_idx];

    for (int i = 0; i < n_in; ++i) {
        if (i == wq_idx) continue;
        long long s = in_sizes[i];
        if (s == 1)                              wscale = (const float*)d_in[i];
        else if (s == ntok_ll)                   ids    = (const int*)d_in[i];
        else if (s == (long long)RANK * D_MODEL) Bm     = (const float*)d_in[i];
        else                                     A      = (const float*)d_in[i];
    }

    const int ntok = (int)ntok_ll;                        // 16384
    dim3 grid(D_MODEL / COLT, (ntok + TOKT - 1) / TOKT);  // (32, 128)
    emb_lora_mma<<<grid, THREADS>>>(ids, wq, wscale, A, Bm, (float*)d_out, ntok);
}